// round 6
// baseline (speedup 1.0000x reference)
#include <cuda_runtime.h>
#include <cuda_bf16.h>
#include <cstdint>
#include <math.h>

#define EDIM 128
#define NTH  512

// ---- dynamic smem byte offsets ----
#define B_HI   0u        // c hi plane  [n=128][k=128] bf16 swizzled
#define B_MID  32768u    // c mid plane
#define A_HI   65536u    // x hi plane  [m=128][k=128]
#define A_MID  98304u    // x mid plane
#define STAGE  131072u   // raw x staging, 64 KB (thread-private 128B regions)
#define O_CSQ  196608u   // float[128]
#define O_RAD  197120u   // float[128]
#define O_XSQ  197632u   // float[128]
#define O_KEYP 198144u   // u32[128][8]
#define O_SROW 202240u   // float[128]
#define O_JROW 202752u   // int[128]
#define SMEM_TOTAL 203264u

#define REFINE_T 1e-2f

__device__ __forceinline__ uint32_t smem_u32(const void* p) {
    uint32_t a;
    asm("{ .reg .u64 t; cvta.to.shared.u64 t, %1; cvt.u32.u64 %0, t; }" : "=r"(a) : "l"(p));
    return a;
}
// swizzled byte offset of 16B chunk kc (0..15) in row n of a [128 rows][256B] plane
__device__ __forceinline__ uint32_t bswz(uint32_t n, uint32_t kc) {
    return n * 256u + ((((kc ^ n) & 7u) | (kc & 8u)) << 4);
}
__device__ __forceinline__ uint32_t cvt_hi2(float lo, float hi) {
    uint32_t r;
    asm("cvt.rn.bf16x2.f32 %0, %1, %2;" : "=r"(r) : "f"(hi), "f"(lo));
    return r;
}
__device__ __forceinline__ uint32_t cvt_mid2(float lo, float hi, uint32_t h) {
    float hlo = __uint_as_float(h << 16);
    float hhi = __uint_as_float(h & 0xFFFF0000u);
    return cvt_hi2(lo - hlo, hi - hhi);
}
__device__ __forceinline__ void ldm_x4(uint32_t* r, uint32_t addr) {
    asm volatile("ldmatrix.sync.aligned.m8n8.x4.shared.b16 {%0,%1,%2,%3}, [%4];"
                 : "=r"(r[0]), "=r"(r[1]), "=r"(r[2]), "=r"(r[3]) : "r"(addr));
}
__device__ __forceinline__ void mma16816(float* d, const uint32_t* a, const uint32_t* b) {
    asm volatile("mma.sync.aligned.m16n8k16.row.col.f32.bf16.bf16.f32 "
                 "{%0,%1,%2,%3}, {%4,%5,%6,%7}, {%8,%9}, {%0,%1,%2,%3};"
                 : "+f"(d[0]), "+f"(d[1]), "+f"(d[2]), "+f"(d[3])
                 : "r"(a[0]), "r"(a[1]), "r"(a[2]), "r"(a[3]), "r"(b[0]), "r"(b[1]));
}
__device__ __forceinline__ uint32_t f2ord(float f) {
    uint32_t u = __float_as_uint(f);
    return (u & 0x80000000u) ? ~u : (u | 0x80000000u);
}
__device__ __forceinline__ float ord2f(uint32_t o) {
    uint32_t u = (o & 0x80000000u) ? (o ^ 0x80000000u) : ~o;
    return __uint_as_float(u);
}
__device__ __forceinline__ float blo(uint32_t w) { return __uint_as_float(w << 16); }
__device__ __forceinline__ float bhi(uint32_t w) { return __uint_as_float(w & 0xFFFF0000u); }
__device__ __forceinline__ float2 rec2(uint32_t h, uint32_t m) {
    return make_float2(blo(h) + blo(m), bhi(h) + bhi(m));
}
__device__ __forceinline__ float exact_d2(const float4* __restrict__ xp,
                                          const float4* __restrict__ cp) {
    float a0 = 0.f, a1 = 0.f;
#pragma unroll 8
    for (int q = 0; q < 32; q++) {
        float4 xv = __ldg(xp + q), cv = __ldg(cp + q);
        float t0 = xv.x - cv.x, t1 = xv.y - cv.y;
        float t2 = xv.z - cv.z, t3 = xv.w - cv.w;
        a0 = fmaf(t0, t0, a0); a1 = fmaf(t1, t1, a1);
        a0 = fmaf(t2, t2, a0); a1 = fmaf(t3, t3, a1);
    }
    return a0 + a1;
}
__device__ __forceinline__ void cpasync16(uint32_t saddr, const void* g) {
    asm volatile("cp.async.cg.shared.global [%0], [%1], 16;" :: "r"(saddr), "l"(g));
}
#define CP_COMMIT() asm volatile("cp.async.commit_group;" ::: "memory")
#define CP_WAIT0()  asm volatile("cp.async.wait_group 0;" ::: "memory")

// convert 16B chunk (8 floats) -> hi/mid planes at plane_hi (+32768 for mid)
__device__ __forceinline__ float cvt_chunk(char* sm, uint32_t plane_hi, uint32_t n,
                                           uint32_t kc, const float4& fa,
                                           const float4& fb, float acc) {
    uint32_t h0 = cvt_hi2(fa.x, fa.y), h1 = cvt_hi2(fa.z, fa.w);
    uint32_t h2 = cvt_hi2(fb.x, fb.y), h3 = cvt_hi2(fb.z, fb.w);
    uint32_t m0 = cvt_mid2(fa.x, fa.y, h0), m1 = cvt_mid2(fa.z, fa.w, h1);
    uint32_t m2 = cvt_mid2(fb.x, fb.y, h2), m3 = cvt_mid2(fb.z, fb.w, h3);
    acc = fmaf(fa.x, fa.x, acc); acc = fmaf(fa.y, fa.y, acc);
    acc = fmaf(fa.z, fa.z, acc); acc = fmaf(fa.w, fa.w, acc);
    acc = fmaf(fb.x, fb.x, acc); acc = fmaf(fb.y, fb.y, acc);
    acc = fmaf(fb.z, fb.z, acc); acc = fmaf(fb.w, fb.w, acc);
    uint32_t o = bswz(n, kc);
    *reinterpret_cast<uint4*>(sm + plane_hi + o)          = make_uint4(h0, h1, h2, h3);
    *reinterpret_cast<uint4*>(sm + plane_hi + 32768u + o) = make_uint4(m0, m1, m2, m3);
    return acc;
}

__global__ void __launch_bounds__(NTH, 1)
attractor_mma3(const float* __restrict__ xg, const float* __restrict__ cg,
               const float* __restrict__ radg, float* __restrict__ out,
               int Brows, int write_idx)
{
    extern __shared__ char smraw[];
    const uint32_t sb = smem_u32(smraw);
    float* csq  = (float*)(smraw + O_CSQ);
    float* rad  = (float*)(smraw + O_RAD);
    float* xsq  = (float*)(smraw + O_XSQ);
    uint32_t* keyp = (uint32_t*)(smraw + O_KEYP);
    float* srow = (float*)(smraw + O_SROW);
    int*   jrow = (int*)(smraw + O_JROW);

    const int tid    = threadIdx.x;
    const int lane   = tid & 31;
    const int wid    = tid >> 5;
    const int warp_m = wid >> 2;   // 0..3 -> rows warp_m*32
    const int warp_n = wid & 3;    // 0..3 -> cols warp_n*32
    const int NT     = (Brows + 127) >> 7;
    const int stride = gridDim.x;

    const int cr = tid >> 2;       // row handled by this thread in convert/epilogue
    const int cq = tid & 3;        // 32-float quarter of that row
    const uint32_t my_stage = STAGE + (uint32_t)tid * 128u;

    if (tid < 128) rad[tid] = radg[tid];

    // ---- prologue: stage x tile(blockIdx.x) ----
    {
        long long rowg = (long long)blockIdx.x * 128 + cr;
        if (rowg >= Brows) rowg = Brows - 1;
        const char* gp = (const char*)(xg + rowg * EDIM + cq * 32);
#pragma unroll
        for (int i = 0; i < 8; i++) cpasync16(sb + my_stage + i * 16, gp + i * 16);
        CP_COMMIT();
    }

    // ---- setup: convert c -> B planes + csq (quad-shuffle reduce) ----
    {
        const float4* cp = reinterpret_cast<const float4*>(cg + cr * EDIM + cq * 32);
        float acc = 0.f;
#pragma unroll
        for (int i = 0; i < 4; i++)
            acc = cvt_chunk(smraw, B_HI, (uint32_t)cr, (uint32_t)(cq * 4 + i),
                            cp[2 * i], cp[2 * i + 1], acc);
        acc += __shfl_xor_sync(0xffffffffu, acc, 1);
        acc += __shfl_xor_sync(0xffffffffu, acc, 2);
        if (cq == 0) csq[cr] = acc;
    }
    __syncthreads();

    // lane-invariant fragment address parts
    const uint32_t arow = (uint32_t)(warp_m * 32 + (lane & 15));
    const uint32_t akh  = (uint32_t)(lane >> 4);
    const uint32_t bn4  = (uint32_t)(warp_n * 32 + ((lane >> 4) << 3) + (lane & 7));
    const uint32_t bkh  = (uint32_t)((lane >> 3) & 1);

    // ---- persistent tile loop ----
    for (int t = blockIdx.x; t < NT; t += stride) {
        const long long row0 = (long long)t << 7;

        // convert x tile from staging -> A planes + xsq
        CP_WAIT0();
        {
            const float4* xp = reinterpret_cast<const float4*>(smraw + my_stage);
            float acc = 0.f;
#pragma unroll
            for (int i = 0; i < 4; i++)
                acc = cvt_chunk(smraw, A_HI, (uint32_t)cr, (uint32_t)(cq * 4 + i),
                                xp[2 * i], xp[2 * i + 1], acc);
            acc += __shfl_xor_sync(0xffffffffu, acc, 1);
            acc += __shfl_xor_sync(0xffffffffu, acc, 2);
            if (cq == 0) xsq[cr] = acc;
        }
        __syncthreads();

        // prefetch next tile's x into staging (flies under MMA/argmin/epilogue)
        {
            int tn = t + stride;
            if (tn < NT) {
                long long rowg = (long long)tn * 128 + cr;
                if (rowg >= Brows) rowg = Brows - 1;
                const char* gp = (const char*)(xg + rowg * EDIM + cq * 32);
#pragma unroll
                for (int i = 0; i < 8; i++) cpasync16(sb + my_stage + i * 16, gp + i * 16);
                CP_COMMIT();
            }
        }

        // ---- MMA mainloop: warp tile 32x32, 3 split passes ----
        float acc[2][4][4];
#pragma unroll
        for (int a = 0; a < 2; a++)
#pragma unroll
            for (int b = 0; b < 4; b++)
#pragma unroll
                for (int e = 0; e < 4; e++) acc[a][b][e] = 0.f;

#pragma unroll
        for (int ch = 0; ch < 8; ch++) {
            uint32_t ah[2][4], am[2][4];
            const uint32_t akc = (uint32_t)ch * 2 + akh;
#pragma unroll
            for (int mt = 0; mt < 2; mt++) {
                uint32_t o = bswz(arow + (uint32_t)mt * 16, akc);
                ldm_x4(ah[mt], sb + A_HI + o);
                ldm_x4(am[mt], sb + A_MID + o);
            }
            uint32_t bh[4][2], bm[4][2];
            const uint32_t bkc = (uint32_t)ch * 2 + bkh;
#pragma unroll
            for (int n2 = 0; n2 < 2; n2++) {
                uint32_t o = bswz(bn4 + (uint32_t)n2 * 16, bkc);
                uint32_t fh[4], fm[4];
                ldm_x4(fh, sb + B_HI + o);
                ldm_x4(fm, sb + B_MID + o);
                bh[2 * n2][0] = fh[0]; bh[2 * n2][1] = fh[1];
                bh[2 * n2 + 1][0] = fh[2]; bh[2 * n2 + 1][1] = fh[3];
                bm[2 * n2][0] = fm[0]; bm[2 * n2][1] = fm[1];
                bm[2 * n2 + 1][0] = fm[2]; bm[2 * n2 + 1][1] = fm[3];
            }
#pragma unroll
            for (int mt = 0; mt < 2; mt++)
#pragma unroll
                for (int nt = 0; nt < 4; nt++) {
                    mma16816(acc[mt][nt], ah[mt], bh[nt]);
                    mma16816(acc[mt][nt], ah[mt], bm[nt]);
                    mma16816(acc[mt][nt], am[mt], bh[nt]);
                }
        }

        // ---- per-row top-2 over this warp's 32 cols (u32 packed keys) ----
#pragma unroll
        for (int mt = 0; mt < 2; mt++) {
#pragma unroll
            for (int s = 0; s < 2; s++) {
                uint32_t k1 = ~0u, k2 = ~0u;
#pragma unroll
                for (int nt = 0; nt < 4; nt++) {
#pragma unroll
                    for (int e = 0; e < 2; e++) {
                        int col = warp_n * 32 + nt * 8 + (lane & 3) * 2 + e;
                        float sc = fmaf(-2.f, acc[mt][nt][s * 2 + e], csq[col]);
                        uint32_t kk = (f2ord(sc) & 0xFFFFFF80u) | (uint32_t)col;
                        if (kk < k1) { k2 = k1; k1 = kk; }
                        else if (kk < k2) k2 = kk;
                    }
                }
#pragma unroll
                for (int m = 1; m < 4; m <<= 1) {
                    uint32_t o1 = __shfl_xor_sync(0xffffffffu, k1, m);
                    uint32_t o2 = __shfl_xor_sync(0xffffffffu, k2, m);
                    if (o1 < k1) { k2 = (k1 < o2) ? k1 : o2; k1 = o1; }
                    else         { k2 = (k2 < o1) ? k2 : o1; }
                }
                if ((lane & 3) == 0) {
                    int rloc = warp_m * 32 + mt * 16 + (lane >> 2) + s * 8;
                    keyp[rloc * 8 + warp_n * 2 + 0] = k1;
                    keyp[rloc * 8 + warp_n * 2 + 1] = k2;
                }
            }
        }
        __syncthreads();

        // ---- merge 4 warp-column results; refine only tight rows ----
        if (tid < 128) {
            uint32_t g1 = ~0u, g2 = ~0u;
#pragma unroll
            for (int w = 0; w < 4; w++) {
                uint32_t o1 = keyp[tid * 8 + w * 2 + 0];
                uint32_t o2 = keyp[tid * 8 + w * 2 + 1];
                if (o1 < g1) { g2 = (g1 < o2) ? g1 : o2; g1 = o1; }
                else         { g2 = (g2 < o1) ? g2 : o1; }
            }
            int j = (int)(g1 & 127u);
            long long rowg = row0 + tid;
            float s1 = ord2f(g1 & 0xFFFFFF80u);
            float s2 = ord2f(g2 & 0xFFFFFF80u);
            float d2;
            if (s2 - s1 < REFINE_T && rowg < Brows) {
                const float4* xp4 = reinterpret_cast<const float4*>(xg + rowg * EDIM);
                int jb = (int)(g2 & 127u);
                float d2a = exact_d2(xp4, reinterpret_cast<const float4*>(cg + (long long)j * EDIM));
                float d2b = exact_d2(xp4, reinterpret_cast<const float4*>(cg + (long long)jb * EDIM));
                if (d2b < d2a || (d2b == d2a && jb < j)) { j = jb; d2a = d2b; }
                d2 = d2a;
            } else {
                d2 = xsq[tid] + s1;
            }
            float dist = sqrtf(fmaxf(d2, 0.f));
            float strength = expf(-dist / (rad[j] + 1e-8f));
            srow[tid] = 0.1f * strength;
            jrow[tid] = j;
            if (write_idx && rowg < Brows)
                out[(long long)Brows * EDIM + rowg] = (float)j;
        }
        __syncthreads();

        // ---- output: attracted = x*(1-s) + c[j]*s, reconstructed from smem planes ----
        {
            long long rowg = row0 + cr;
            if (rowg < Brows) {
                float s = srow[cr];
                int j = jrow[cr];
                float om = 1.f - s;
                float4* op = reinterpret_cast<float4*>(out + rowg * EDIM + cq * 32);
#pragma unroll
                for (int i = 0; i < 4; i++) {
                    uint32_t ox = bswz((uint32_t)cr, (uint32_t)(cq * 4 + i));
                    uint32_t oc = bswz((uint32_t)j, (uint32_t)(cq * 4 + i));
                    uint4 xh = *reinterpret_cast<uint4*>(smraw + A_HI + ox);
                    uint4 xm = *reinterpret_cast<uint4*>(smraw + A_MID + ox);
                    uint4 chv = *reinterpret_cast<uint4*>(smraw + B_HI + oc);
                    uint4 cmv = *reinterpret_cast<uint4*>(smraw + B_MID + oc);
                    float2 x0 = rec2(xh.x, xm.x), x1 = rec2(xh.y, xm.y);
                    float2 x2 = rec2(xh.z, xm.z), x3 = rec2(xh.w, xm.w);
                    float2 c0 = rec2(chv.x, cmv.x), c1 = rec2(chv.y, cmv.y);
                    float2 c2 = rec2(chv.z, cmv.z), c3 = rec2(chv.w, cmv.w);
                    float4 o0, o1;
                    o0.x = fmaf(c0.x, s, x0.x * om); o0.y = fmaf(c0.y, s, x0.y * om);
                    o0.z = fmaf(c1.x, s, x1.x * om); o0.w = fmaf(c1.y, s, x1.y * om);
                    o1.x = fmaf(c2.x, s, x2.x * om); o1.y = fmaf(c2.y, s, x2.y * om);
                    o1.z = fmaf(c3.x, s, x3.x * om); o1.w = fmaf(c3.y, s, x3.y * om);
                    op[2 * i]     = o0;
                    op[2 * i + 1] = o1;
                }
            }
        }
        __syncthreads();   // A planes free for next tile's convert
    }
}

extern "C" void kernel_launch(void* const* d_in, const int* in_sizes, int n_in,
                              void* d_out, int out_size)
{
    const float* x     = (const float*)d_in[0];
    const float* c     = (const float*)d_in[1];
    const float* radii = (const float*)d_in[2];
    float* out = (float*)d_out;

    int Brows = in_sizes[0] / EDIM;
    int write_idx = (out_size >= Brows * (EDIM + 1)) ? 1 : 0;

    int sms = 148;
    cudaDeviceGetAttribute(&sms, cudaDevAttrMultiProcessorCount, 0);
    int nt = (Brows + 127) / 128;
    int grid = sms < nt ? sms : nt;

    cudaFuncSetAttribute(attractor_mma3,
                         cudaFuncAttributeMaxDynamicSharedMemorySize, (int)SMEM_TOTAL);
    attractor_mma3<<<grid, NTH, SMEM_TOTAL>>>(x, c, radii, out, Brows, write_idx);
}

// round 7
// speedup vs baseline: 1.1798x; 1.1798x over previous
#include <cuda_runtime.h>
#include <cuda_bf16.h>
#include <cstdint>
#include <math.h>

#define EDIM 128
#define NTH  512

// ---- dynamic smem byte offsets ----
#define B_HI    0u        // c hi plane [n=128][k=128] bf16 swizzled (+32768 = mid)
#define A_PL0   65536u    // x planes buffer 0 (hi @0, mid @+32768)
#define A_PL1   131072u   // x planes buffer 1
#define APL_XOR 196608u   // A_PL0 ^ A_PL1 flip mask (0x30000)
#define O_CSQ   196608u   // float[128]
#define O_RAD   197120u   // float[128]
#define O_XSQ   197632u   // float[128]
#define O_KEYP  198144u   // u64[128][4][2] = 8192 B
#define O_SROW  206336u   // float[128]
#define O_JROW  206848u   // int[128]
#define SMEM_TOTAL 207360u

#define REFINE_T 1e-3f

__device__ __forceinline__ uint32_t smem_u32(const void* p) {
    uint32_t a;
    asm("{ .reg .u64 t; cvta.to.shared.u64 t, %1; cvt.u32.u64 %0, t; }" : "=r"(a) : "l"(p));
    return a;
}
// swizzled byte offset of 16B chunk kc (0..15) in row n of a [128 rows][256B] plane
__device__ __forceinline__ uint32_t bswz(uint32_t n, uint32_t kc) {
    return n * 256u + ((((kc ^ n) & 7u) | (kc & 8u)) << 4);
}
__device__ __forceinline__ uint32_t cvt_hi2(float lo, float hi) {
    uint32_t r;
    asm("cvt.rn.bf16x2.f32 %0, %1, %2;" : "=r"(r) : "f"(hi), "f"(lo));
    return r;
}
__device__ __forceinline__ uint32_t cvt_mid2(float lo, float hi, uint32_t h) {
    float hlo = __uint_as_float(h << 16);
    float hhi = __uint_as_float(h & 0xFFFF0000u);
    return cvt_hi2(lo - hlo, hi - hhi);
}
__device__ __forceinline__ void ldm_x4(uint32_t* r, uint32_t addr) {
    asm volatile("ldmatrix.sync.aligned.m8n8.x4.shared.b16 {%0,%1,%2,%3}, [%4];"
                 : "=r"(r[0]), "=r"(r[1]), "=r"(r[2]), "=r"(r[3]) : "r"(addr));
}
__device__ __forceinline__ void mma16816(float* d, const uint32_t* a, const uint32_t* b) {
    asm volatile("mma.sync.aligned.m16n8k16.row.col.f32.bf16.bf16.f32 "
                 "{%0,%1,%2,%3}, {%4,%5,%6,%7}, {%8,%9}, {%0,%1,%2,%3};"
                 : "+f"(d[0]), "+f"(d[1]), "+f"(d[2]), "+f"(d[3])
                 : "r"(a[0]), "r"(a[1]), "r"(a[2]), "r"(a[3]), "r"(b[0]), "r"(b[1]));
}
#define STS64A(addr, a, b) \
    asm volatile("st.shared.v2.b32 [%0], {%1,%2};" :: "r"(addr), "r"(a), "r"(b) : "memory")
#define LDS64A(a, b, addr) \
    asm volatile("ld.shared.v2.b32 {%0,%1}, [%2];" : "=r"(a), "=r"(b) : "r"(addr))

__device__ __forceinline__ uint32_t f2ord(float f) {
    uint32_t u = __float_as_uint(f);
    return (u & 0x80000000u) ? ~u : (u | 0x80000000u);
}
__device__ __forceinline__ float ord2f(uint32_t o) {
    uint32_t u = (o & 0x80000000u) ? (o ^ 0x80000000u) : ~o;
    return __uint_as_float(u);
}
__device__ __forceinline__ float blo(uint32_t w) { return __uint_as_float(w << 16); }
__device__ __forceinline__ float bhi(uint32_t w) { return __uint_as_float(w & 0xFFFF0000u); }
__device__ __forceinline__ float2 rec2(uint32_t h, uint32_t m) {
    return make_float2(blo(h) + blo(m), bhi(h) + bhi(m));
}
__device__ __forceinline__ float exact_d2(const float4* __restrict__ xp,
                                          const float4* __restrict__ cp) {
    float a0 = 0.f, a1 = 0.f;
#pragma unroll 8
    for (int q = 0; q < 32; q++) {
        float4 xv = __ldg(xp + q), cv = __ldg(cp + q);
        float t0 = xv.x - cv.x, t1 = xv.y - cv.y;
        float t2 = xv.z - cv.z, t3 = xv.w - cv.w;
        a0 = fmaf(t0, t0, a0); a1 = fmaf(t1, t1, a1);
        a0 = fmaf(t2, t2, a0); a1 = fmaf(t3, t3, a1);
    }
    return a0 + a1;
}

// coalesced row-band loads: warp=8 rows, lane=(row=l&7, quad g=l>>3)
__device__ __forceinline__ void load_row_quads(float4* v, const float* __restrict__ base,
                                               long long row, int g) {
    const float4* gp = reinterpret_cast<const float4*>(base + row * EDIM) + g;
#pragma unroll
    for (int i = 0; i < 8; i++) v[i] = __ldg(gp + 4 * i);
}
// convert 8 float4s (quads g, g+4, ... of row rowloc) -> hi/mid planes; row-sum to sqout
__device__ __forceinline__ void cvt_regs_to_planes(uint32_t sb, uint32_t plane_hi,
                                                   int rowloc, int g, const float4* v,
                                                   float* sqout, int lane) {
    float acc = 0.f;
#pragma unroll
    for (int i = 0; i < 8; i++) {
        float4 f = v[i];
        int c4 = g + 4 * i;
        uint32_t kc = (uint32_t)(c4 >> 1), hf = (uint32_t)(c4 & 1) * 8u;
        uint32_t h0 = cvt_hi2(f.x, f.y), h1 = cvt_hi2(f.z, f.w);
        uint32_t m0 = cvt_mid2(f.x, f.y, h0), m1 = cvt_mid2(f.z, f.w, h1);
        acc = fmaf(f.x, f.x, acc); acc = fmaf(f.y, f.y, acc);
        acc = fmaf(f.z, f.z, acc); acc = fmaf(f.w, f.w, acc);
        uint32_t o = sb + plane_hi + bswz((uint32_t)rowloc, kc) + hf;
        STS64A(o, h0, h1);
        STS64A(o + 32768u, m0, m1);
    }
    acc += __shfl_xor_sync(0xffffffffu, acc, 8);
    acc += __shfl_xor_sync(0xffffffffu, acc, 16);
    if (g == 0) sqout[rowloc] = acc;
}

__global__ void __launch_bounds__(NTH, 1)
attractor_mma4(const float* __restrict__ xg, const float* __restrict__ cg,
               const float* __restrict__ radg, float* __restrict__ out,
               int Brows, int write_idx)
{
    extern __shared__ char smraw[];
    const uint32_t sb = smem_u32(smraw);
    float* csq  = (float*)(smraw + O_CSQ);
    float* rad  = (float*)(smraw + O_RAD);
    float* xsq  = (float*)(smraw + O_XSQ);
    unsigned long long* keyp = (unsigned long long*)(smraw + O_KEYP);
    float* srow = (float*)(smraw + O_SROW);
    int*   jrow = (int*)(smraw + O_JROW);

    const int tid    = threadIdx.x;
    const int lane   = tid & 31;
    const int wid    = tid >> 5;
    const int warp_m = wid >> 2;
    const int warp_n = wid & 3;
    const int NT     = (Brows + 127) >> 7;
    const int stride = gridDim.x;

    const int rowloc = (wid << 3) + (lane & 7);   // convert/output row (0..127)
    const int g      = lane >> 3;                 // quad group (0..3)

    if (tid < 128) rad[tid] = radg[tid];

    // ---- prologue: convert c -> B planes (+csq), convert tile0 x -> A_PL0 (+xsq) ----
    {
        float4 vb[8];
        load_row_quads(vb, cg, (long long)rowloc, g);
        cvt_regs_to_planes(sb, B_HI, rowloc, g, vb, csq, lane);
        long long rowg = (long long)blockIdx.x * 128 + rowloc;
        if (rowg >= Brows) rowg = Brows - 1;
        float4 va[8];
        load_row_quads(va, xg, rowg, g);
        cvt_regs_to_planes(sb, A_PL0, rowloc, g, va, xsq, lane);
    }
    __syncthreads();

    // hoist this thread's 8 csq values into registers (stable all kernel)
    float csr[8];
#pragma unroll
    for (int nt = 0; nt < 4; nt++)
#pragma unroll
        for (int e = 0; e < 2; e++)
            csr[nt * 2 + e] = csq[warp_n * 32 + nt * 8 + (lane & 3) * 2 + e];

    // lane-invariant fragment address parts
    const uint32_t arow = (uint32_t)(warp_m * 32 + (lane & 15));
    const uint32_t akh  = (uint32_t)(lane >> 4);
    const uint32_t bn4  = (uint32_t)(warp_n * 32 + ((lane >> 4) << 3) + (lane & 7));
    const uint32_t bkh  = (uint32_t)((lane >> 3) & 1);

    uint32_t APH = A_PL0;

    // ---- persistent tile loop ----
    for (int t = blockIdx.x; t < NT; t += stride) {
        const long long row0 = (long long)t << 7;

        // ---- MMA mainloop: warp tile 32x32, 3 split passes ----
        float acc[2][4][4];
#pragma unroll
        for (int a = 0; a < 2; a++)
#pragma unroll
            for (int bq = 0; bq < 4; bq++)
#pragma unroll
                for (int e = 0; e < 4; e++) acc[a][bq][e] = 0.f;

#pragma unroll
        for (int ch = 0; ch < 8; ch++) {
            uint32_t ah[2][4], am[2][4];
            const uint32_t akc = (uint32_t)ch * 2 + akh;
#pragma unroll
            for (int mt = 0; mt < 2; mt++) {
                uint32_t o = bswz(arow + (uint32_t)mt * 16, akc);
                ldm_x4(ah[mt], sb + APH + o);
                ldm_x4(am[mt], sb + APH + 32768u + o);
            }
            uint32_t bh[4][2], bm[4][2];
            const uint32_t bkc = (uint32_t)ch * 2 + bkh;
#pragma unroll
            for (int n2 = 0; n2 < 2; n2++) {
                uint32_t o = bswz(bn4 + (uint32_t)n2 * 16, bkc);
                uint32_t fh[4], fm[4];
                ldm_x4(fh, sb + B_HI + o);
                ldm_x4(fm, sb + B_HI + 32768u + o);
                bh[2 * n2][0] = fh[0]; bh[2 * n2][1] = fh[1];
                bh[2 * n2 + 1][0] = fh[2]; bh[2 * n2 + 1][1] = fh[3];
                bm[2 * n2][0] = fm[0]; bm[2 * n2][1] = fm[1];
                bm[2 * n2 + 1][0] = fm[2]; bm[2 * n2 + 1][1] = fm[3];
            }
#pragma unroll
            for (int mt = 0; mt < 2; mt++)
#pragma unroll
                for (int nt = 0; nt < 4; nt++) {
                    mma16816(acc[mt][nt], ah[mt], bh[nt]);
                    mma16816(acc[mt][nt], ah[mt], bm[nt]);
                    mma16816(acc[mt][nt], am[mt], bh[nt]);
                }
        }

        // ---- per-row top-2 over this warp's 32 cols (u64 keys, exact score) ----
#pragma unroll
        for (int mt = 0; mt < 2; mt++) {
#pragma unroll
            for (int s = 0; s < 2; s++) {
                unsigned long long k1 = ~0ull, k2 = ~0ull;
#pragma unroll
                for (int nt = 0; nt < 4; nt++) {
#pragma unroll
                    for (int e = 0; e < 2; e++) {
                        int col = warp_n * 32 + nt * 8 + (lane & 3) * 2 + e;
                        float sc = fmaf(-2.f, acc[mt][nt][s * 2 + e], csr[nt * 2 + e]);
                        unsigned long long kk =
                            ((unsigned long long)f2ord(sc) << 32) | (unsigned)col;
                        if (kk < k1) { k2 = k1; k1 = kk; }
                        else if (kk < k2) k2 = kk;
                    }
                }
#pragma unroll
                for (int m = 1; m < 4; m <<= 1) {
                    unsigned long long o1 = __shfl_xor_sync(0xffffffffu, k1, m);
                    unsigned long long o2 = __shfl_xor_sync(0xffffffffu, k2, m);
                    if (o1 < k1) { k2 = (k1 < o2) ? k1 : o2; k1 = o1; }
                    else         { k2 = (k2 < o1) ? k2 : o1; }
                }
                if ((lane & 3) == 0) {
                    int rloc = warp_m * 32 + mt * 16 + (lane >> 2) + s * 8;
                    keyp[rloc * 8 + warp_n * 2 + 0] = k1;
                    keyp[rloc * 8 + warp_n * 2 + 1] = k2;
                }
            }
        }
        __syncthreads();

        // ---- merge 4 warp-column results; refine only near-ties ----
        if (tid < 128) {
            unsigned long long g1 = ~0ull, g2 = ~0ull;
#pragma unroll
            for (int w = 0; w < 4; w++) {
                unsigned long long o1 = keyp[tid * 8 + w * 2 + 0];
                unsigned long long o2 = keyp[tid * 8 + w * 2 + 1];
                if (o1 < g1) { g2 = (g1 < o2) ? g1 : o2; g1 = o1; }
                else         { g2 = (g2 < o1) ? g2 : o1; }
            }
            int j = (int)(g1 & 0xFFFFFFFFull);
            long long rowg = row0 + tid;
            float s1 = ord2f((uint32_t)(g1 >> 32));
            float s2 = ord2f((uint32_t)(g2 >> 32));
            float d2;
            if (s2 - s1 < REFINE_T && rowg < Brows) {
                const float4* xp4 = reinterpret_cast<const float4*>(xg + rowg * EDIM);
                int jb = (int)(g2 & 0xFFFFFFFFull);
                float d2a = exact_d2(xp4, reinterpret_cast<const float4*>(cg + (long long)j * EDIM));
                float d2b = exact_d2(xp4, reinterpret_cast<const float4*>(cg + (long long)jb * EDIM));
                if (d2b < d2a || (d2b == d2a && jb < j)) { j = jb; d2a = d2b; }
                d2 = d2a;
            } else {
                d2 = xsq[tid] + s1;
            }
            float dist = sqrtf(fmaxf(d2, 0.f));
            float strength = expf(-dist / (rad[j] + 1e-8f));
            srow[tid] = 0.1f * strength;
            jrow[tid] = j;
            if (write_idx && rowg < Brows)
                out[(long long)Brows * EDIM + rowg] = (float)j;
        }
        __syncthreads();

        // ---- merged phase: prefetch x(t+stride), output(t), convert into A(b^1) ----
        {
            int tn = t + stride;
            bool hn = (tn < NT);
            float4 v[8];
            if (hn) {
                long long rowg = (long long)tn * 128 + rowloc;
                if (rowg >= Brows) rowg = Brows - 1;
                load_row_quads(v, xg, rowg, g);      // flight hidden under output below
            }
            // output tile t (reads A(b) + B planes)
            long long rowg = row0 + rowloc;
            if (rowg < Brows) {
                float s = srow[rowloc];
                int j = jrow[rowloc];
                float om = 1.f - s;
                float4* op = reinterpret_cast<float4*>(out + rowg * EDIM) + g;
#pragma unroll
                for (int i = 0; i < 8; i++) {
                    int c4 = g + 4 * i;
                    uint32_t kc = (uint32_t)(c4 >> 1), hf = (uint32_t)(c4 & 1) * 8u;
                    uint32_t ox = sb + APH + bswz((uint32_t)rowloc, kc) + hf;
                    uint32_t oc = sb + B_HI + bswz((uint32_t)j, kc) + hf;
                    uint32_t xh0, xh1, xm0, xm1, ch0, ch1, cm0, cm1;
                    LDS64A(xh0, xh1, ox); LDS64A(xm0, xm1, ox + 32768u);
                    LDS64A(ch0, ch1, oc); LDS64A(cm0, cm1, oc + 32768u);
                    float2 x0 = rec2(xh0, xm0), x1 = rec2(xh1, xm1);
                    float2 c0 = rec2(ch0, cm0), c1 = rec2(ch1, cm1);
                    float4 o;
                    o.x = fmaf(c0.x, s, x0.x * om); o.y = fmaf(c0.y, s, x0.y * om);
                    o.z = fmaf(c1.x, s, x1.x * om); o.w = fmaf(c1.y, s, x1.y * om);
                    op[4 * i] = o;
                }
            }
            if (hn)
                cvt_regs_to_planes(sb, APH ^ APL_XOR, rowloc, g, v, xsq, lane);
        }
        __syncthreads();
        APH ^= APL_XOR;
    }
}

extern "C" void kernel_launch(void* const* d_in, const int* in_sizes, int n_in,
                              void* d_out, int out_size)
{
    const float* x     = (const float*)d_in[0];
    const float* c     = (const float*)d_in[1];
    const float* radii = (const float*)d_in[2];
    float* out = (float*)d_out;

    int Brows = in_sizes[0] / EDIM;
    int write_idx = (out_size >= Brows * (EDIM + 1)) ? 1 : 0;

    int sms = 148;
    cudaDeviceGetAttribute(&sms, cudaDevAttrMultiProcessorCount, 0);
    int nt = (Brows + 127) / 128;
    int grid = sms < nt ? sms : nt;

    cudaFuncSetAttribute(attractor_mma4,
                         cudaFuncAttributeMaxDynamicSharedMemorySize, (int)SMEM_TOTAL);
    attractor_mma4<<<grid, NTH, SMEM_TOTAL>>>(x, c, radii, out, Brows, write_idx);
}

// round 8
// speedup vs baseline: 1.3152x; 1.1148x over previous
#include <cuda_runtime.h>
#include <cuda_bf16.h>
#include <cstdint>
#include <math.h>

#define EDIM 128
#define NTH  256
#define TROWS 64   // rows per CTA tile

// ---- dynamic smem byte offsets ----
#define B_HI    0u        // c hi plane [n=128][k=128] swizzled; mid @ +32768
#define A_HI    65536u    // x hi plane [m=64][k=128]; mid @ +16384
#define O_CSQ   98304u    // float[128]
#define O_RAD   98816u    // float[128]
#define O_XSQ   99328u    // float[64]
#define O_KEYP  99584u    // u32[64][8] = 2048
#define O_SROW  101632u   // float[64]
#define O_JROW  101888u   // int[64]
#define SMEM_TOTAL 102144u

#define REFINE_T 4e-3f

__device__ __forceinline__ uint32_t smem_u32(const void* p) {
    uint32_t a;
    asm("{ .reg .u64 t; cvta.to.shared.u64 t, %1; cvt.u32.u64 %0, t; }" : "=r"(a) : "l"(p));
    return a;
}
// swizzled byte offset of 16B chunk kc (0..15) in row n of a [rows][256B] plane
__device__ __forceinline__ uint32_t bswz(uint32_t n, uint32_t kc) {
    return n * 256u + ((((kc ^ n) & 7u) | (kc & 8u)) << 4);
}
__device__ __forceinline__ uint32_t cvt_hi2(float lo, float hi) {
    uint32_t r;
    asm("cvt.rn.bf16x2.f32 %0, %1, %2;" : "=r"(r) : "f"(hi), "f"(lo));
    return r;
}
__device__ __forceinline__ uint32_t cvt_mid2(float lo, float hi, uint32_t h) {
    float hlo = __uint_as_float(h << 16);
    float hhi = __uint_as_float(h & 0xFFFF0000u);
    return cvt_hi2(lo - hlo, hi - hhi);
}
__device__ __forceinline__ void ldm_x4(uint32_t* r, uint32_t addr) {
    asm volatile("ldmatrix.sync.aligned.m8n8.x4.shared.b16 {%0,%1,%2,%3}, [%4];"
                 : "=r"(r[0]), "=r"(r[1]), "=r"(r[2]), "=r"(r[3]) : "r"(addr));
}
__device__ __forceinline__ void mma16816(float* d, const uint32_t* a, const uint32_t* b) {
    asm volatile("mma.sync.aligned.m16n8k16.row.col.f32.bf16.bf16.f32 "
                 "{%0,%1,%2,%3}, {%4,%5,%6,%7}, {%8,%9}, {%0,%1,%2,%3};"
                 : "+f"(d[0]), "+f"(d[1]), "+f"(d[2]), "+f"(d[3])
                 : "r"(a[0]), "r"(a[1]), "r"(a[2]), "r"(a[3]), "r"(b[0]), "r"(b[1]));
}
#define STS64A(addr, a, b) \
    asm volatile("st.shared.v2.b32 [%0], {%1,%2};" :: "r"(addr), "r"(a), "r"(b) : "memory")
#define LDS64A(a, b, addr) \
    asm volatile("ld.shared.v2.b32 {%0,%1}, [%2];" : "=r"(a), "=r"(b) : "r"(addr))

__device__ __forceinline__ uint32_t f2ord(float f) {
    uint32_t u = __float_as_uint(f);
    return (u & 0x80000000u) ? ~u : (u | 0x80000000u);
}
__device__ __forceinline__ float ord2f(uint32_t o) {
    uint32_t u = (o & 0x80000000u) ? (o ^ 0x80000000u) : ~o;
    return __uint_as_float(u);
}
__device__ __forceinline__ float blo(uint32_t w) { return __uint_as_float(w << 16); }
__device__ __forceinline__ float bhi(uint32_t w) { return __uint_as_float(w & 0xFFFF0000u); }
__device__ __forceinline__ float2 rec2(uint32_t h, uint32_t m) {
    return make_float2(blo(h) + blo(m), bhi(h) + bhi(m));
}
__device__ __forceinline__ float exact_d2(const float4* __restrict__ xp,
                                          const float4* __restrict__ cp) {
    float a0 = 0.f, a1 = 0.f;
#pragma unroll 8
    for (int q = 0; q < 32; q++) {
        float4 xv = __ldg(xp + q), cv = __ldg(cp + q);
        float t0 = xv.x - cv.x, t1 = xv.y - cv.y;
        float t2 = xv.z - cv.z, t3 = xv.w - cv.w;
        a0 = fmaf(t0, t0, a0); a1 = fmaf(t1, t1, a1);
        a0 = fmaf(t2, t2, a0); a1 = fmaf(t3, t3, a1);
    }
    return a0 + a1;
}
// coalesced row-band loads: warp=8 rows, lane=(row=l&7, quad g=l>>3)
__device__ __forceinline__ void load_row_quads(float4* v, const float* __restrict__ base,
                                               long long row, int g) {
    const float4* gp = reinterpret_cast<const float4*>(base + row * EDIM) + g;
#pragma unroll
    for (int i = 0; i < 8; i++) v[i] = __ldg(gp + 4 * i);
}
// convert 8 float4s (quads g, g+4,... of row rowloc) -> hi/mid planes; row-sum to sqout
__device__ __forceinline__ void cvt_regs_to_planes(uint32_t sb, uint32_t plane_hi,
                                                   uint32_t mid_off, int rowloc, int g,
                                                   const float4* v, float* sqout) {
    float acc = 0.f;
#pragma unroll
    for (int i = 0; i < 8; i++) {
        float4 f = v[i];
        int c4 = g + 4 * i;
        uint32_t kc = (uint32_t)(c4 >> 1), hf = (uint32_t)(c4 & 1) * 8u;
        uint32_t h0 = cvt_hi2(f.x, f.y), h1 = cvt_hi2(f.z, f.w);
        uint32_t m0 = cvt_mid2(f.x, f.y, h0), m1 = cvt_mid2(f.z, f.w, h1);
        acc = fmaf(f.x, f.x, acc); acc = fmaf(f.y, f.y, acc);
        acc = fmaf(f.z, f.z, acc); acc = fmaf(f.w, f.w, acc);
        uint32_t o = sb + plane_hi + bswz((uint32_t)rowloc, kc) + hf;
        STS64A(o, h0, h1);
        STS64A(o + mid_off, m0, m1);
    }
    acc += __shfl_xor_sync(0xffffffffu, acc, 8);
    acc += __shfl_xor_sync(0xffffffffu, acc, 16);
    if (g == 0) sqout[rowloc] = acc;
}

__global__ void __launch_bounds__(NTH, 2)
attractor_mma5(const float* __restrict__ xg, const float* __restrict__ cg,
               const float* __restrict__ radg, float* __restrict__ out,
               int Brows, int write_idx)
{
    extern __shared__ char smraw[];
    const uint32_t sb = smem_u32(smraw);
    float* csq  = (float*)(smraw + O_CSQ);
    float* rad  = (float*)(smraw + O_RAD);
    float* xsq  = (float*)(smraw + O_XSQ);
    uint32_t* keyp = (uint32_t*)(smraw + O_KEYP);
    float* srow = (float*)(smraw + O_SROW);
    int*   jrow = (int*)(smraw + O_JROW);

    const int tid    = threadIdx.x;
    const int lane   = tid & 31;
    const int wid    = tid >> 5;
    const int warp_m = wid >> 2;   // 0..1 -> rows warp_m*32
    const int warp_n = wid & 3;    // 0..3 -> cols warp_n*32
    const int NT     = (Brows + TROWS - 1) / TROWS;
    const int stride = gridDim.x;

    const int rowloc = (wid << 3) + (lane & 7);   // 0..63
    const int g      = lane >> 3;                 // 0..3

    if (tid < 128) rad[tid] = radg[tid];

    // ---- prologue: convert c (2 rows/thread) -> B planes + csq; x tile0 -> A ----
    {
        float4 vb[8];
        load_row_quads(vb, cg, (long long)rowloc, g);
        cvt_regs_to_planes(sb, B_HI, 32768u, rowloc, g, vb, csq);
        load_row_quads(vb, cg, (long long)(rowloc + 64), g);
        cvt_regs_to_planes(sb, B_HI, 32768u, rowloc + 64, g, vb, csq);
        long long rowg = (long long)blockIdx.x * TROWS + rowloc;
        if (rowg >= Brows) rowg = Brows - 1;
        float4 va[8];
        load_row_quads(va, xg, rowg, g);
        cvt_regs_to_planes(sb, A_HI, 16384u, rowloc, g, va, xsq);
    }
    __syncthreads();

    // hoist this thread's 8 csq values
    float csr[8];
#pragma unroll
    for (int nt = 0; nt < 4; nt++)
#pragma unroll
        for (int e = 0; e < 2; e++)
            csr[nt * 2 + e] = csq[warp_n * 32 + nt * 8 + (lane & 3) * 2 + e];

    const uint32_t arow = (uint32_t)(warp_m * 32 + (lane & 15));
    const uint32_t akh  = (uint32_t)(lane >> 4);
    const uint32_t bn4  = (uint32_t)(warp_n * 32 + ((lane >> 4) << 3) + (lane & 7));
    const uint32_t bkh  = (uint32_t)((lane >> 3) & 1);

    // ---- persistent tile loop ----
    for (int t = blockIdx.x; t < NT; t += stride) {
        const long long row0 = (long long)t * TROWS;

        // ---- MMA mainloop: warp tile 32x32, 3 split passes ----
        float acc[2][4][4];
#pragma unroll
        for (int a = 0; a < 2; a++)
#pragma unroll
            for (int bq = 0; bq < 4; bq++)
#pragma unroll
                for (int e = 0; e < 4; e++) acc[a][bq][e] = 0.f;

#pragma unroll
        for (int ch = 0; ch < 8; ch++) {
            uint32_t ah[2][4], am[2][4];
            const uint32_t akc = (uint32_t)ch * 2 + akh;
#pragma unroll
            for (int mt = 0; mt < 2; mt++) {
                uint32_t o = bswz(arow + (uint32_t)mt * 16, akc);
                ldm_x4(ah[mt], sb + A_HI + o);
                ldm_x4(am[mt], sb + A_HI + 16384u + o);
            }
            uint32_t bh[4][2], bm[4][2];
            const uint32_t bkc = (uint32_t)ch * 2 + bkh;
#pragma unroll
            for (int n2 = 0; n2 < 2; n2++) {
                uint32_t o = bswz(bn4 + (uint32_t)n2 * 16, bkc);
                uint32_t fh[4], fm[4];
                ldm_x4(fh, sb + B_HI + o);
                ldm_x4(fm, sb + B_HI + 32768u + o);
                bh[2 * n2][0] = fh[0]; bh[2 * n2][1] = fh[1];
                bh[2 * n2 + 1][0] = fh[2]; bh[2 * n2 + 1][1] = fh[3];
                bm[2 * n2][0] = fm[0]; bm[2 * n2][1] = fm[1];
                bm[2 * n2 + 1][0] = fm[2]; bm[2 * n2 + 1][1] = fm[3];
            }
#pragma unroll
            for (int mt = 0; mt < 2; mt++)
#pragma unroll
                for (int nt = 0; nt < 4; nt++) {
                    mma16816(acc[mt][nt], ah[mt], bh[nt]);
                    mma16816(acc[mt][nt], ah[mt], bm[nt]);
                    mma16816(acc[mt][nt], am[mt], bh[nt]);
                }
        }

        // ---- per-row top-2 over this warp's 32 cols (u32 packed keys) ----
#pragma unroll
        for (int mt = 0; mt < 2; mt++) {
#pragma unroll
            for (int s = 0; s < 2; s++) {
                uint32_t k1 = ~0u, k2 = ~0u;
#pragma unroll
                for (int nt = 0; nt < 4; nt++) {
#pragma unroll
                    for (int e = 0; e < 2; e++) {
                        int col = warp_n * 32 + nt * 8 + (lane & 3) * 2 + e;
                        float sc = fmaf(-2.f, acc[mt][nt][s * 2 + e], csr[nt * 2 + e]);
                        uint32_t kk = (f2ord(sc) & 0xFFFFFF80u) | (uint32_t)col;
                        if (kk < k1) { k2 = k1; k1 = kk; }
                        else if (kk < k2) k2 = kk;
                    }
                }
#pragma unroll
                for (int m = 1; m < 4; m <<= 1) {
                    uint32_t o1 = __shfl_xor_sync(0xffffffffu, k1, m);
                    uint32_t o2 = __shfl_xor_sync(0xffffffffu, k2, m);
                    if (o1 < k1) { k2 = (k1 < o2) ? k1 : o2; k1 = o1; }
                    else         { k2 = (k2 < o1) ? k2 : o1; }
                }
                if ((lane & 3) == 0) {
                    int rloc = warp_m * 32 + mt * 16 + (lane >> 2) + s * 8;
                    keyp[rloc * 8 + warp_n * 2 + 0] = k1;
                    keyp[rloc * 8 + warp_n * 2 + 1] = k2;
                }
            }
        }
        __syncthreads();

        // ---- merge 4 warp-column results; refine only near-ties ----
        if (tid < TROWS) {
            uint32_t g1 = ~0u, g2 = ~0u;
#pragma unroll
            for (int w = 0; w < 4; w++) {
                uint32_t o1 = keyp[tid * 8 + w * 2 + 0];
                uint32_t o2 = keyp[tid * 8 + w * 2 + 1];
                if (o1 < g1) { g2 = (g1 < o2) ? g1 : o2; g1 = o1; }
                else         { g2 = (g2 < o1) ? g2 : o1; }
            }
            int j = (int)(g1 & 127u);
            long long rowg = row0 + tid;
            float s1 = ord2f(g1 & 0xFFFFFF80u);
            float s2 = ord2f(g2 & 0xFFFFFF80u);
            float d2;
            if (s2 - s1 < REFINE_T && rowg < Brows) {
                const float4* xp4 = reinterpret_cast<const float4*>(xg + rowg * EDIM);
                int jb = (int)(g2 & 127u);
                float d2a = exact_d2(xp4, reinterpret_cast<const float4*>(cg + (long long)j * EDIM));
                float d2b = exact_d2(xp4, reinterpret_cast<const float4*>(cg + (long long)jb * EDIM));
                if (d2b < d2a || (d2b == d2a && jb < j)) { j = jb; d2a = d2b; }
                d2 = d2a;
            } else {
                d2 = xsq[tid] + s1;
            }
            float dist = sqrtf(fmaxf(d2, 0.f));
            float strength = expf(-dist / (rad[j] + 1e-8f));
            srow[tid] = 0.1f * strength;
            jrow[tid] = j;
            if (write_idx && rowg < Brows)
                out[(long long)Brows * EDIM + rowg] = (float)j;
        }
        __syncthreads();

        // ---- output(t): prefetch next x first, then blend from smem planes ----
        int tn = t + stride;
        bool hn = (tn < NT);
        float4 v[8];
        if (hn) {
            long long rowg = (long long)tn * TROWS + rowloc;
            if (rowg >= Brows) rowg = Brows - 1;
            load_row_quads(v, xg, rowg, g);   // flight hides under output below
        }
        {
            long long rowg = row0 + rowloc;
            if (rowg < Brows) {
                float s = srow[rowloc];
                int j = jrow[rowloc];
                float om = 1.f - s;
                float4* op = reinterpret_cast<float4*>(out + rowg * EDIM) + g;
#pragma unroll
                for (int i = 0; i < 8; i++) {
                    int c4 = g + 4 * i;
                    uint32_t kc = (uint32_t)(c4 >> 1), hf = (uint32_t)(c4 & 1) * 8u;
                    uint32_t ox = sb + A_HI + bswz((uint32_t)rowloc, kc) + hf;
                    uint32_t oc = sb + B_HI + bswz((uint32_t)j, kc) + hf;
                    uint32_t xh0, xh1, xm0, xm1, ch0, ch1, cm0, cm1;
                    LDS64A(xh0, xh1, ox); LDS64A(xm0, xm1, ox + 16384u);
                    LDS64A(ch0, ch1, oc); LDS64A(cm0, cm1, oc + 32768u);
                    float2 x0 = rec2(xh0, xm0), x1 = rec2(xh1, xm1);
                    float2 c0 = rec2(ch0, cm0), c1 = rec2(ch1, cm1);
                    float4 o;
                    o.x = fmaf(c0.x, s, x0.x * om); o.y = fmaf(c0.y, s, x0.y * om);
                    o.z = fmaf(c1.x, s, x1.x * om); o.w = fmaf(c1.y, s, x1.y * om);
                    op[4 * i] = o;
                }
            }
        }
        __syncthreads();   // A planes free

        if (hn)
            cvt_regs_to_planes(sb, A_HI, 16384u, rowloc, g, v, xsq);
        __syncthreads();
    }
}

extern "C" void kernel_launch(void* const* d_in, const int* in_sizes, int n_in,
                              void* d_out, int out_size)
{
    const float* x     = (const float*)d_in[0];
    const float* c     = (const float*)d_in[1];
    const float* radii = (const float*)d_in[2];
    float* out = (float*)d_out;

    int Brows = in_sizes[0] / EDIM;
    int write_idx = (out_size >= Brows * (EDIM + 1)) ? 1 : 0;

    int sms = 148;
    cudaDeviceGetAttribute(&sms, cudaDevAttrMultiProcessorCount, 0);
    int nt = (Brows + TROWS - 1) / TROWS;
    int grid = 2 * sms < nt ? 2 * sms : nt;

    cudaFuncSetAttribute(attractor_mma5,
                         cudaFuncAttributeMaxDynamicSharedMemorySize, (int)SMEM_TOTAL);
    attractor_mma5<<<grid, NTH, SMEM_TOTAL>>>(x, c, radii, out, Brows, write_idx);
}

// round 9
// speedup vs baseline: 1.3664x; 1.0389x over previous
#include <cuda_runtime.h>
#include <cuda_fp16.h>
#include <cstdint>
#include <math.h>

#define EDIM 128
#define NTH  256
#define TROWS 64   // rows per CTA tile

// ---- dynamic smem byte offsets ----
#define B_HI    0u        // c hi plane [n=128][k=128] fp16 swizzled
#define B_MID   32768u    // c mid plane
#define A_HI    65536u    // x hi plane [m=64][k=128] fp16 (no mid plane)
#define O_CSQ   81920u    // float[128]
#define O_RAD   82432u    // float[128]
#define O_XSQ   82944u    // float[64]
#define O_KEYP  83200u    // u32[64][8] = 2048
#define O_SROW  85248u    // float[64]
#define O_JROW  85504u    // int[64]
#define SMEM_TOTAL 85760u

#define REFINE_T 1.5e-2f

__device__ __forceinline__ uint32_t smem_u32(const void* p) {
    uint32_t a;
    asm("{ .reg .u64 t; cvta.to.shared.u64 t, %1; cvt.u32.u64 %0, t; }" : "=r"(a) : "l"(p));
    return a;
}
// swizzled byte offset of 16B chunk kc (0..15) in row n of a [rows][256B] plane
__device__ __forceinline__ uint32_t bswz(uint32_t n, uint32_t kc) {
    return n * 256u + ((((kc ^ n) & 7u) | (kc & 8u)) << 4);
}
// pack two f32 -> f16x2 (lo in low half)
__device__ __forceinline__ uint32_t pack_h2(float lo, float hi) {
    uint32_t r;
    asm("cvt.rn.f16x2.f32 %0, %1, %2;" : "=r"(r) : "f"(hi), "f"(lo));
    return r;
}
// unpack f16x2 -> two f32
__device__ __forceinline__ float2 h2f2(uint32_t w) {
    float2 r;
    asm("{ .reg .f16 l, h; mov.b32 {l, h}, %2; cvt.f32.f16 %0, l; cvt.f32.f16 %1, h; }"
        : "=f"(r.x), "=f"(r.y) : "r"(w));
    return r;
}
__device__ __forceinline__ void ldm_x4(uint32_t* r, uint32_t addr) {
    asm volatile("ldmatrix.sync.aligned.m8n8.x4.shared.b16 {%0,%1,%2,%3}, [%4];"
                 : "=r"(r[0]), "=r"(r[1]), "=r"(r[2]), "=r"(r[3]) : "r"(addr));
}
__device__ __forceinline__ void mma16816(float* d, const uint32_t* a, const uint32_t* b) {
    asm volatile("mma.sync.aligned.m16n8k16.row.col.f32.f16.f16.f32 "
                 "{%0,%1,%2,%3}, {%4,%5,%6,%7}, {%8,%9}, {%0,%1,%2,%3};"
                 : "+f"(d[0]), "+f"(d[1]), "+f"(d[2]), "+f"(d[3])
                 : "r"(a[0]), "r"(a[1]), "r"(a[2]), "r"(a[3]), "r"(b[0]), "r"(b[1]));
}
#define STS64A(addr, a, b) \
    asm volatile("st.shared.v2.b32 [%0], {%1,%2};" :: "r"(addr), "r"(a), "r"(b) : "memory")
#define LDS64A(a, b, addr) \
    asm volatile("ld.shared.v2.b32 {%0,%1}, [%2];" : "=r"(a), "=r"(b) : "r"(addr))

__device__ __forceinline__ uint32_t f2ord(float f) {
    uint32_t u = __float_as_uint(f);
    return (u & 0x80000000u) ? ~u : (u | 0x80000000u);
}
__device__ __forceinline__ float ord2f(uint32_t o) {
    uint32_t u = (o & 0x80000000u) ? (o ^ 0x80000000u) : ~o;
    return __uint_as_float(u);
}
__device__ __forceinline__ float exact_d2(const float4* __restrict__ xp,
                                          const float4* __restrict__ cp) {
    float a0 = 0.f, a1 = 0.f;
#pragma unroll 8
    for (int q = 0; q < 32; q++) {
        float4 xv = __ldg(xp + q), cv = __ldg(cp + q);
        float t0 = xv.x - cv.x, t1 = xv.y - cv.y;
        float t2 = xv.z - cv.z, t3 = xv.w - cv.w;
        a0 = fmaf(t0, t0, a0); a1 = fmaf(t1, t1, a1);
        a0 = fmaf(t2, t2, a0); a1 = fmaf(t3, t3, a1);
    }
    return a0 + a1;
}
// coalesced row-band loads: warp=8 rows, lane=(row=l&7, quad g=l>>3)
__device__ __forceinline__ void load_row_quads(float4* v, const float* __restrict__ base,
                                               long long row, int g) {
    const float4* gp = reinterpret_cast<const float4*>(base + row * EDIM) + g;
#pragma unroll
    for (int i = 0; i < 8; i++) v[i] = __ldg(gp + 4 * i);
}
// B convert: 8 float4s -> hi+mid fp16 planes; exact f32 row-sum to sqout
__device__ __forceinline__ void cvtB(uint32_t sb, int rowloc, int g, const float4* v,
                                     float* sqout) {
    float acc = 0.f;
#pragma unroll
    for (int i = 0; i < 8; i++) {
        float4 f = v[i];
        int c4 = g + 4 * i;
        uint32_t kc = (uint32_t)(c4 >> 1), hf = (uint32_t)(c4 & 1) * 8u;
        uint32_t h0 = pack_h2(f.x, f.y), h1 = pack_h2(f.z, f.w);
        float2 r0 = h2f2(h0), r1 = h2f2(h1);
        uint32_t m0 = pack_h2(f.x - r0.x, f.y - r0.y);
        uint32_t m1 = pack_h2(f.z - r1.x, f.w - r1.y);
        acc = fmaf(f.x, f.x, acc); acc = fmaf(f.y, f.y, acc);
        acc = fmaf(f.z, f.z, acc); acc = fmaf(f.w, f.w, acc);
        uint32_t o = sb + B_HI + bswz((uint32_t)rowloc, kc) + hf;
        STS64A(o, h0, h1);
        STS64A(o + 32768u, m0, m1);
    }
    acc += __shfl_xor_sync(0xffffffffu, acc, 8);
    acc += __shfl_xor_sync(0xffffffffu, acc, 16);
    if (g == 0) sqout[rowloc] = acc;
}
// A convert: hi plane only; exact f32 row-sum to sqout
__device__ __forceinline__ void cvtA(uint32_t sb, int rowloc, int g, const float4* v,
                                     float* sqout) {
    float acc = 0.f;
#pragma unroll
    for (int i = 0; i < 8; i++) {
        float4 f = v[i];
        int c4 = g + 4 * i;
        uint32_t kc = (uint32_t)(c4 >> 1), hf = (uint32_t)(c4 & 1) * 8u;
        uint32_t h0 = pack_h2(f.x, f.y), h1 = pack_h2(f.z, f.w);
        acc = fmaf(f.x, f.x, acc); acc = fmaf(f.y, f.y, acc);
        acc = fmaf(f.z, f.z, acc); acc = fmaf(f.w, f.w, acc);
        STS64A(sb + A_HI + bswz((uint32_t)rowloc, kc) + hf, h0, h1);
    }
    acc += __shfl_xor_sync(0xffffffffu, acc, 8);
    acc += __shfl_xor_sync(0xffffffffu, acc, 16);
    if (g == 0) sqout[rowloc] = acc;
}

__global__ void __launch_bounds__(NTH, 2)
attractor_mma6(const float* __restrict__ xg, const float* __restrict__ cg,
               const float* __restrict__ radg, float* __restrict__ out,
               int Brows, int write_idx)
{
    extern __shared__ char smraw[];
    const uint32_t sb = smem_u32(smraw);
    float* csq  = (float*)(smraw + O_CSQ);
    float* rad  = (float*)(smraw + O_RAD);
    float* xsq  = (float*)(smraw + O_XSQ);
    uint32_t* keyp = (uint32_t*)(smraw + O_KEYP);
    float* srow = (float*)(smraw + O_SROW);
    int*   jrow = (int*)(smraw + O_JROW);

    const int tid    = threadIdx.x;
    const int lane   = tid & 31;
    const int wid    = tid >> 5;
    const int warp_m = wid >> 2;   // 0..1
    const int warp_n = wid & 3;    // 0..3
    const int NT     = (Brows + TROWS - 1) / TROWS;
    const int stride = gridDim.x;

    const int rowloc = (wid << 3) + (lane & 7);   // 0..63
    const int g      = lane >> 3;                 // 0..3

    if (tid < 128) rad[tid] = radg[tid];

    // ---- prologue: c -> B planes (+csq); x tile0 -> A hi (+xsq) ----
    {
        float4 vb[8];
        load_row_quads(vb, cg, (long long)rowloc, g);
        cvtB(sb, rowloc, g, vb, csq);
        load_row_quads(vb, cg, (long long)(rowloc + 64), g);
        cvtB(sb, rowloc + 64, g, vb, csq);
        long long rowg = (long long)blockIdx.x * TROWS + rowloc;
        if (rowg >= Brows) rowg = Brows - 1;
        float4 va[8];
        load_row_quads(va, xg, rowg, g);
        cvtA(sb, rowloc, g, va, xsq);
    }
    __syncthreads();

    float csr[8];
#pragma unroll
    for (int nt = 0; nt < 4; nt++)
#pragma unroll
        for (int e = 0; e < 2; e++)
            csr[nt * 2 + e] = csq[warp_n * 32 + nt * 8 + (lane & 3) * 2 + e];

    const uint32_t arow = (uint32_t)(warp_m * 32 + (lane & 15));
    const uint32_t akh  = (uint32_t)(lane >> 4);
    const uint32_t bn4  = (uint32_t)(warp_n * 32 + ((lane >> 4) << 3) + (lane & 7));
    const uint32_t bkh  = (uint32_t)((lane >> 3) & 1);

    // ---- persistent tile loop ----
    for (int t = blockIdx.x; t < NT; t += stride) {
        const long long row0 = (long long)t * TROWS;

        // ---- MMA mainloop: warp tile 32x32, 2 passes (hh + hm) ----
        float acc[2][4][4];
#pragma unroll
        for (int a = 0; a < 2; a++)
#pragma unroll
            for (int bq = 0; bq < 4; bq++)
#pragma unroll
                for (int e = 0; e < 4; e++) acc[a][bq][e] = 0.f;

#pragma unroll
        for (int ch = 0; ch < 8; ch++) {
            uint32_t ah[2][4];
            const uint32_t akc = (uint32_t)ch * 2 + akh;
#pragma unroll
            for (int mt = 0; mt < 2; mt++)
                ldm_x4(ah[mt], sb + A_HI + bswz(arow + (uint32_t)mt * 16, akc));
            uint32_t bh[4][2], bm[4][2];
            const uint32_t bkc = (uint32_t)ch * 2 + bkh;
#pragma unroll
            for (int n2 = 0; n2 < 2; n2++) {
                uint32_t o = bswz(bn4 + (uint32_t)n2 * 16, bkc);
                uint32_t fh[4], fm[4];
                ldm_x4(fh, sb + B_HI + o);
                ldm_x4(fm, sb + B_MID + o);
                bh[2 * n2][0] = fh[0]; bh[2 * n2][1] = fh[1];
                bh[2 * n2 + 1][0] = fh[2]; bh[2 * n2 + 1][1] = fh[3];
                bm[2 * n2][0] = fm[0]; bm[2 * n2][1] = fm[1];
                bm[2 * n2 + 1][0] = fm[2]; bm[2 * n2 + 1][1] = fm[3];
            }
#pragma unroll
            for (int mt = 0; mt < 2; mt++)
#pragma unroll
                for (int nt = 0; nt < 4; nt++) {
                    mma16816(acc[mt][nt], ah[mt], bh[nt]);
                    mma16816(acc[mt][nt], ah[mt], bm[nt]);
                }
        }

        // ---- per-row top-2 over this warp's 32 cols (u32 packed keys) ----
#pragma unroll
        for (int mt = 0; mt < 2; mt++) {
#pragma unroll
            for (int s = 0; s < 2; s++) {
                uint32_t k1 = ~0u, k2 = ~0u;
#pragma unroll
                for (int nt = 0; nt < 4; nt++) {
#pragma unroll
                    for (int e = 0; e < 2; e++) {
                        int col = warp_n * 32 + nt * 8 + (lane & 3) * 2 + e;
                        float sc = fmaf(-2.f, acc[mt][nt][s * 2 + e], csr[nt * 2 + e]);
                        uint32_t kk = (f2ord(sc) & 0xFFFFFF80u) | (uint32_t)col;
                        if (kk < k1) { k2 = k1; k1 = kk; }
                        else if (kk < k2) k2 = kk;
                    }
                }
#pragma unroll
                for (int m = 1; m < 4; m <<= 1) {
                    uint32_t o1 = __shfl_xor_sync(0xffffffffu, k1, m);
                    uint32_t o2 = __shfl_xor_sync(0xffffffffu, k2, m);
                    if (o1 < k1) { k2 = (k1 < o2) ? k1 : o2; k1 = o1; }
                    else         { k2 = (k2 < o1) ? k2 : o1; }
                }
                if ((lane & 3) == 0) {
                    int rloc = warp_m * 32 + mt * 16 + (lane >> 2) + s * 8;
                    keyp[rloc * 8 + warp_n * 2 + 0] = k1;
                    keyp[rloc * 8 + warp_n * 2 + 1] = k2;
                }
            }
        }
        __syncthreads();

        // ---- merge; refine near-ties exactly ----
        if (tid < TROWS) {
            uint32_t g1 = ~0u, g2 = ~0u;
#pragma unroll
            for (int w = 0; w < 4; w++) {
                uint32_t o1 = keyp[tid * 8 + w * 2 + 0];
                uint32_t o2 = keyp[tid * 8 + w * 2 + 1];
                if (o1 < g1) { g2 = (g1 < o2) ? g1 : o2; g1 = o1; }
                else         { g2 = (g2 < o1) ? g2 : o1; }
            }
            int j = (int)(g1 & 127u);
            long long rowg = row0 + tid;
            float s1 = ord2f(g1 & 0xFFFFFF80u);
            float s2 = ord2f(g2 & 0xFFFFFF80u);
            float d2;
            if (s2 - s1 < REFINE_T && rowg < Brows) {
                const float4* xp4 = reinterpret_cast<const float4*>(xg + rowg * EDIM);
                int jb = (int)(g2 & 127u);
                float d2a = exact_d2(xp4, reinterpret_cast<const float4*>(cg + (long long)j * EDIM));
                float d2b = exact_d2(xp4, reinterpret_cast<const float4*>(cg + (long long)jb * EDIM));
                if (d2b < d2a || (d2b == d2a && jb < j)) { j = jb; d2a = d2b; }
                d2 = d2a;
            } else {
                d2 = xsq[tid] + s1;
            }
            float dist = sqrtf(fmaxf(d2, 0.f));
            float strength = expf(-dist / (rad[j] + 1e-8f));
            srow[tid] = 0.1f * strength;
            jrow[tid] = j;
            if (write_idx && rowg < Brows)
                out[(long long)Brows * EDIM + rowg] = (float)j;
        }
        __syncthreads();

        // ---- output(t): prefetch next x, then blend (x from A-hi, c from gmem/L2) ----
        int tn = t + stride;
        bool hn = (tn < NT);
        float4 v[8];
        if (hn) {
            long long rowg = (long long)tn * TROWS + rowloc;
            if (rowg >= Brows) rowg = Brows - 1;
            load_row_quads(v, xg, rowg, g);   // flight hides under output below
        }
        {
            long long rowg = row0 + rowloc;
            if (rowg < Brows) {
                float s = srow[rowloc];
                int j = jrow[rowloc];
                float om = 1.f - s;
                const float4* cj = reinterpret_cast<const float4*>(cg + (long long)j * EDIM);
                float4* op = reinterpret_cast<float4*>(out + rowg * EDIM);
#pragma unroll
                for (int i = 0; i < 8; i++) {
                    int c4 = g + 4 * i;
                    uint32_t kc = (uint32_t)(c4 >> 1), hf = (uint32_t)(c4 & 1) * 8u;
                    uint32_t xh0, xh1;
                    LDS64A(xh0, xh1, sb + A_HI + bswz((uint32_t)rowloc, kc) + hf);
                    float2 x0 = h2f2(xh0), x1 = h2f2(xh1);
                    float4 cv = __ldg(cj + c4);
                    float4 o;
                    o.x = fmaf(cv.x, s, x0.x * om); o.y = fmaf(cv.y, s, x0.y * om);
                    o.z = fmaf(cv.z, s, x1.x * om); o.w = fmaf(cv.w, s, x1.y * om);
                    op[c4] = o;
                }
            }
        }
        __syncthreads();   // A plane free

        if (hn)
            cvtA(sb, rowloc, g, v, xsq);
        __syncthreads();
    }
}

extern "C" void kernel_launch(void* const* d_in, const int* in_sizes, int n_in,
                              void* d_out, int out_size)
{
    const float* x     = (const float*)d_in[0];
    const float* c     = (const float*)d_in[1];
    const float* radii = (const float*)d_in[2];
    float* out = (float*)d_out;

    int Brows = in_sizes[0] / EDIM;
    int write_idx = (out_size >= Brows * (EDIM + 1)) ? 1 : 0;

    int sms = 148;
    cudaDeviceGetAttribute(&sms, cudaDevAttrMultiProcessorCount, 0);
    int nt = (Brows + TROWS - 1) / TROWS;
    int grid = 2 * sms < nt ? 2 * sms : nt;

    cudaFuncSetAttribute(attractor_mma6,
                         cudaFuncAttributeMaxDynamicSharedMemorySize, (int)SMEM_TOTAL);
    attractor_mma6<<<grid, NTH, SMEM_TOTAL>>>(x, c, radii, out, Brows, write_idx);
}

// round 10
// speedup vs baseline: 1.5482x; 1.1330x over previous
#include <cuda_runtime.h>
#include <cuda_fp16.h>
#include <cstdint>
#include <math.h>

#define EDIM 128
#define NTH  256
#define TROWS 64   // rows per CTA tile (kernel 1)
#define BMAX 524288

// ---- kernel-1 dynamic smem byte offsets ----
#define B_HI    0u        // c hi plane [n=128][k=128] fp16 swizzled
#define B_MID   32768u    // c mid plane
#define A_HI    65536u    // x hi plane [m=64][k=128] fp16
#define O_CSQ   81920u    // float[128]
#define O_RAD   82432u    // float[128]
#define O_XSQ   82944u    // float[64]
#define O_KEYP  83200u    // u32[64][8] = 2048
#define SMEM_K1 85248u

#define REFINE_T 1.5e-2f

// scratch for strength + index between the two kernels
__device__ float g_s[BMAX];
__device__ int   g_j[BMAX];

__device__ __forceinline__ uint32_t smem_u32(const void* p) {
    uint32_t a;
    asm("{ .reg .u64 t; cvta.to.shared.u64 t, %1; cvt.u32.u64 %0, t; }" : "=r"(a) : "l"(p));
    return a;
}
__device__ __forceinline__ uint32_t bswz(uint32_t n, uint32_t kc) {
    return n * 256u + ((((kc ^ n) & 7u) | (kc & 8u)) << 4);
}
__device__ __forceinline__ uint32_t pack_h2(float lo, float hi) {
    uint32_t r;
    asm("cvt.rn.f16x2.f32 %0, %1, %2;" : "=r"(r) : "f"(hi), "f"(lo));
    return r;
}
__device__ __forceinline__ float2 h2f2(uint32_t w) {
    float2 r;
    asm("{ .reg .f16 l, h; mov.b32 {l, h}, %2; cvt.f32.f16 %0, l; cvt.f32.f16 %1, h; }"
        : "=f"(r.x), "=f"(r.y) : "r"(w));
    return r;
}
__device__ __forceinline__ void ldm_x4(uint32_t* r, uint32_t addr) {
    asm volatile("ldmatrix.sync.aligned.m8n8.x4.shared.b16 {%0,%1,%2,%3}, [%4];"
                 : "=r"(r[0]), "=r"(r[1]), "=r"(r[2]), "=r"(r[3]) : "r"(addr));
}
__device__ __forceinline__ void mma16816(float* d, const uint32_t* a, const uint32_t* b) {
    asm volatile("mma.sync.aligned.m16n8k16.row.col.f32.f16.f16.f32 "
                 "{%0,%1,%2,%3}, {%4,%5,%6,%7}, {%8,%9}, {%0,%1,%2,%3};"
                 : "+f"(d[0]), "+f"(d[1]), "+f"(d[2]), "+f"(d[3])
                 : "r"(a[0]), "r"(a[1]), "r"(a[2]), "r"(a[3]), "r"(b[0]), "r"(b[1]));
}
#define STS64A(addr, a, b) \
    asm volatile("st.shared.v2.b32 [%0], {%1,%2};" :: "r"(addr), "r"(a), "r"(b) : "memory")

__device__ __forceinline__ uint32_t f2ord(float f) {
    uint32_t u = __float_as_uint(f);
    return (u & 0x80000000u) ? ~u : (u | 0x80000000u);
}
__device__ __forceinline__ float ord2f(uint32_t o) {
    uint32_t u = (o & 0x80000000u) ? (o ^ 0x80000000u) : ~o;
    return __uint_as_float(u);
}
__device__ __forceinline__ float exact_d2(const float4* __restrict__ xp,
                                          const float4* __restrict__ cp) {
    float a0 = 0.f, a1 = 0.f;
#pragma unroll 8
    for (int q = 0; q < 32; q++) {
        float4 xv = __ldg(xp + q), cv = __ldg(cp + q);
        float t0 = xv.x - cv.x, t1 = xv.y - cv.y;
        float t2 = xv.z - cv.z, t3 = xv.w - cv.w;
        a0 = fmaf(t0, t0, a0); a1 = fmaf(t1, t1, a1);
        a0 = fmaf(t2, t2, a0); a1 = fmaf(t3, t3, a1);
    }
    return a0 + a1;
}
__device__ __forceinline__ void load_row_quads(float4* v, const float* __restrict__ base,
                                               long long row, int g) {
    const float4* gp = reinterpret_cast<const float4*>(base + row * EDIM) + g;
#pragma unroll
    for (int i = 0; i < 8; i++) v[i] = __ldg(gp + 4 * i);
}
// B convert: hi+mid fp16 planes; exact f32 row-sum to sqout
__device__ __forceinline__ void cvtB(uint32_t sb, int rowloc, int g, const float4* v,
                                     float* sqout) {
    float acc = 0.f;
#pragma unroll
    for (int i = 0; i < 8; i++) {
        float4 f = v[i];
        int c4 = g + 4 * i;
        uint32_t kc = (uint32_t)(c4 >> 1), hf = (uint32_t)(c4 & 1) * 8u;
        uint32_t h0 = pack_h2(f.x, f.y), h1 = pack_h2(f.z, f.w);
        float2 r0 = h2f2(h0), r1 = h2f2(h1);
        uint32_t m0 = pack_h2(f.x - r0.x, f.y - r0.y);
        uint32_t m1 = pack_h2(f.z - r1.x, f.w - r1.y);
        acc = fmaf(f.x, f.x, acc); acc = fmaf(f.y, f.y, acc);
        acc = fmaf(f.z, f.z, acc); acc = fmaf(f.w, f.w, acc);
        uint32_t o = sb + B_HI + bswz((uint32_t)rowloc, kc) + hf;
        STS64A(o, h0, h1);
        STS64A(o + 32768u, m0, m1);
    }
    acc += __shfl_xor_sync(0xffffffffu, acc, 8);
    acc += __shfl_xor_sync(0xffffffffu, acc, 16);
    if (g == 0) sqout[rowloc] = acc;
}
// A convert: hi plane only; exact f32 row-sum to sqout
__device__ __forceinline__ void cvtA(uint32_t sb, int rowloc, int g, const float4* v,
                                     float* sqout) {
    float acc = 0.f;
#pragma unroll
    for (int i = 0; i < 8; i++) {
        float4 f = v[i];
        int c4 = g + 4 * i;
        uint32_t kc = (uint32_t)(c4 >> 1), hf = (uint32_t)(c4 & 1) * 8u;
        uint32_t h0 = pack_h2(f.x, f.y), h1 = pack_h2(f.z, f.w);
        acc = fmaf(f.x, f.x, acc); acc = fmaf(f.y, f.y, acc);
        acc = fmaf(f.z, f.z, acc); acc = fmaf(f.w, f.w, acc);
        STS64A(sb + A_HI + bswz((uint32_t)rowloc, kc) + hf, h0, h1);
    }
    acc += __shfl_xor_sync(0xffffffffu, acc, 8);
    acc += __shfl_xor_sync(0xffffffffu, acc, 16);
    if (g == 0) sqout[rowloc] = acc;
}

// ============================ kernel 1: argmin ============================
__global__ void __launch_bounds__(NTH, 2)
argmin_kernel(const float* __restrict__ xg, const float* __restrict__ cg,
              const float* __restrict__ radg, float* __restrict__ out,
              int Brows, int write_idx)
{
    extern __shared__ char smraw[];
    const uint32_t sb = smem_u32(smraw);
    float* csq  = (float*)(smraw + O_CSQ);
    float* rad  = (float*)(smraw + O_RAD);
    float* xsq  = (float*)(smraw + O_XSQ);
    uint32_t* keyp = (uint32_t*)(smraw + O_KEYP);

    const int tid    = threadIdx.x;
    const int lane   = tid & 31;
    const int wid    = tid >> 5;
    const int warp_m = wid >> 2;   // 0..1
    const int warp_n = wid & 3;    // 0..3
    const int NT     = (Brows + TROWS - 1) / TROWS;
    const int stride = gridDim.x;

    const int rowloc = (wid << 3) + (lane & 7);   // 0..63
    const int g      = lane >> 3;                 // 0..3

    if (tid < 128) rad[tid] = radg[tid];

    // prologue: c -> B planes (+csq); x tile0 -> A hi (+xsq)
    {
        float4 vb[8];
        load_row_quads(vb, cg, (long long)rowloc, g);
        cvtB(sb, rowloc, g, vb, csq);
        load_row_quads(vb, cg, (long long)(rowloc + 64), g);
        cvtB(sb, rowloc + 64, g, vb, csq);
        long long rowg = (long long)blockIdx.x * TROWS + rowloc;
        if (rowg >= Brows) rowg = Brows - 1;
        float4 va[8];
        load_row_quads(va, xg, rowg, g);
        cvtA(sb, rowloc, g, va, xsq);
    }
    __syncthreads();

    float csr[8];
#pragma unroll
    for (int nt = 0; nt < 4; nt++)
#pragma unroll
        for (int e = 0; e < 2; e++)
            csr[nt * 2 + e] = csq[warp_n * 32 + nt * 8 + (lane & 3) * 2 + e];

    const uint32_t arow = (uint32_t)(warp_m * 32 + (lane & 15));
    const uint32_t akh  = (uint32_t)(lane >> 4);
    const uint32_t bn4  = (uint32_t)(warp_n * 32 + ((lane >> 4) << 3) + (lane & 7));
    const uint32_t bkh  = (uint32_t)((lane >> 3) & 1);

    for (int t = blockIdx.x; t < NT; t += stride) {
        const long long row0 = (long long)t * TROWS;

        // ---- MMA mainloop: warp tile 32x32, passes hh + hm ----
        float acc[2][4][4];
#pragma unroll
        for (int a = 0; a < 2; a++)
#pragma unroll
            for (int bq = 0; bq < 4; bq++)
#pragma unroll
                for (int e = 0; e < 4; e++) acc[a][bq][e] = 0.f;

#pragma unroll
        for (int ch = 0; ch < 8; ch++) {
            uint32_t ah[2][4];
            const uint32_t akc = (uint32_t)ch * 2 + akh;
#pragma unroll
            for (int mt = 0; mt < 2; mt++)
                ldm_x4(ah[mt], sb + A_HI + bswz(arow + (uint32_t)mt * 16, akc));
            uint32_t bh[4][2], bm[4][2];
            const uint32_t bkc = (uint32_t)ch * 2 + bkh;
#pragma unroll
            for (int n2 = 0; n2 < 2; n2++) {
                uint32_t o = bswz(bn4 + (uint32_t)n2 * 16, bkc);
                uint32_t fh[4], fm[4];
                ldm_x4(fh, sb + B_HI + o);
                ldm_x4(fm, sb + B_MID + o);
                bh[2 * n2][0] = fh[0]; bh[2 * n2][1] = fh[1];
                bh[2 * n2 + 1][0] = fh[2]; bh[2 * n2 + 1][1] = fh[3];
                bm[2 * n2][0] = fm[0]; bm[2 * n2][1] = fm[1];
                bm[2 * n2 + 1][0] = fm[2]; bm[2 * n2 + 1][1] = fm[3];
            }
#pragma unroll
            for (int mt = 0; mt < 2; mt++)
#pragma unroll
                for (int nt = 0; nt < 4; nt++) {
                    mma16816(acc[mt][nt], ah[mt], bh[nt]);
                    mma16816(acc[mt][nt], ah[mt], bm[nt]);
                }
        }

        // ---- per-row top-2 over this warp's 32 cols (u32 packed keys) ----
#pragma unroll
        for (int mt = 0; mt < 2; mt++) {
#pragma unroll
            for (int s = 0; s < 2; s++) {
                uint32_t k1 = ~0u, k2 = ~0u;
#pragma unroll
                for (int nt = 0; nt < 4; nt++) {
#pragma unroll
                    for (int e = 0; e < 2; e++) {
                        int col = warp_n * 32 + nt * 8 + (lane & 3) * 2 + e;
                        float sc = fmaf(-2.f, acc[mt][nt][s * 2 + e], csr[nt * 2 + e]);
                        uint32_t kk = (f2ord(sc) & 0xFFFFFF80u) | (uint32_t)col;
                        if (kk < k1) { k2 = k1; k1 = kk; }
                        else if (kk < k2) k2 = kk;
                    }
                }
#pragma unroll
                for (int m = 1; m < 4; m <<= 1) {
                    uint32_t o1 = __shfl_xor_sync(0xffffffffu, k1, m);
                    uint32_t o2 = __shfl_xor_sync(0xffffffffu, k2, m);
                    if (o1 < k1) { k2 = (k1 < o2) ? k1 : o2; k1 = o1; }
                    else         { k2 = (k2 < o1) ? k2 : o1; }
                }
                if ((lane & 3) == 0) {
                    int rloc = warp_m * 32 + mt * 16 + (lane >> 2) + s * 8;
                    keyp[rloc * 8 + warp_n * 2 + 0] = k1;
                    keyp[rloc * 8 + warp_n * 2 + 1] = k2;
                }
            }
        }
        __syncthreads();

        // ---- prefetch next tile's x (flight hides under merge) ----
        int tn = t + stride;
        bool hn = (tn < NT);
        float4 v[8];
        if (hn) {
            long long rowg = (long long)tn * TROWS + rowloc;
            if (rowg >= Brows) rowg = Brows - 1;
            load_row_quads(v, xg, rowg, g);
        }

        // ---- merge; refine near-ties; emit idx + strength ----
        if (tid < TROWS) {
            uint32_t g1 = ~0u, g2 = ~0u;
#pragma unroll
            for (int w = 0; w < 4; w++) {
                uint32_t o1 = keyp[tid * 8 + w * 2 + 0];
                uint32_t o2 = keyp[tid * 8 + w * 2 + 1];
                if (o1 < g1) { g2 = (g1 < o2) ? g1 : o2; g1 = o1; }
                else         { g2 = (g2 < o1) ? g2 : o1; }
            }
            int j = (int)(g1 & 127u);
            long long rowg = row0 + tid;
            if (rowg < Brows) {
                float s1 = ord2f(g1 & 0xFFFFFF80u);
                float s2 = ord2f(g2 & 0xFFFFFF80u);
                float d2;
                if (s2 - s1 < REFINE_T) {
                    const float4* xp4 = reinterpret_cast<const float4*>(xg + rowg * EDIM);
                    int jb = (int)(g2 & 127u);
                    float d2a = exact_d2(xp4, reinterpret_cast<const float4*>(cg + (long long)j * EDIM));
                    float d2b = exact_d2(xp4, reinterpret_cast<const float4*>(cg + (long long)jb * EDIM));
                    if (d2b < d2a || (d2b == d2a && jb < j)) { j = jb; d2a = d2b; }
                    d2 = d2a;
                } else {
                    d2 = xsq[tid] + s1;
                }
                float dist = sqrtf(fmaxf(d2, 0.f));
                float strength = expf(-dist / (rad[j] + 1e-8f));
                g_s[rowg] = 0.1f * strength;
                g_j[rowg] = j;
                if (write_idx)
                    out[(long long)Brows * EDIM + rowg] = (float)j;
            }
        }
        __syncthreads();

        if (hn) cvtA(sb, rowloc, g, v, xsq);
        __syncthreads();
    }
}

// ============================ kernel 2: blend =============================
__global__ void __launch_bounds__(256)
blend_kernel(const float* __restrict__ xg, const float* __restrict__ cg,
             float* __restrict__ out, int Brows)
{
    const float4* x4 = reinterpret_cast<const float4*>(xg);
    const float4* c4 = reinterpret_cast<const float4*>(cg);
    float4* o4 = reinterpret_cast<float4*>(out);
    const long long total = (long long)Brows * 32;
    const long long step = (long long)gridDim.x * blockDim.x;
    for (long long f = (long long)blockIdx.x * blockDim.x + threadIdx.x; f < total; f += step) {
        long long row = f >> 5;
        int q = (int)(f & 31);
        int j = g_j[row];          // uniform across warp -> broadcast
        float s = g_s[row];
        float om = 1.f - s;
        float4 xv = __ldg(x4 + row * 32 + q);
        float4 cv = __ldg(c4 + (long long)j * 32 + q);
        float4 o;
        o.x = fmaf(cv.x, s, xv.x * om);
        o.y = fmaf(cv.y, s, xv.y * om);
        o.z = fmaf(cv.z, s, xv.z * om);
        o.w = fmaf(cv.w, s, xv.w * om);
        o4[row * 32 + q] = o;
    }
}

extern "C" void kernel_launch(void* const* d_in, const int* in_sizes, int n_in,
                              void* d_out, int out_size)
{
    const float* x     = (const float*)d_in[0];
    const float* c     = (const float*)d_in[1];
    const float* radii = (const float*)d_in[2];
    float* out = (float*)d_out;

    int Brows = in_sizes[0] / EDIM;
    if (Brows > BMAX) Brows = BMAX;
    int write_idx = (out_size >= Brows * (EDIM + 1)) ? 1 : 0;

    int sms = 148;
    cudaDeviceGetAttribute(&sms, cudaDevAttrMultiProcessorCount, 0);
    int nt = (Brows + TROWS - 1) / TROWS;
    int grid1 = 2 * sms < nt ? 2 * sms : nt;

    cudaFuncSetAttribute(argmin_kernel,
                         cudaFuncAttributeMaxDynamicSharedMemorySize, (int)SMEM_K1);
    argmin_kernel<<<grid1, NTH, SMEM_K1>>>(x, c, radii, out, Brows, write_idx);

    int grid2 = sms * 8;
    blend_kernel<<<grid2, 256>>>(x, c, out, Brows);
}